// round 6
// baseline (speedup 1.0000x reference)
#include <cuda_runtime.h>
#include <cuda_fp16.h>
#include <math.h>

#define N_NODES 8192
#define F_IN    256
#define F_OUT   128
#define MAXNBR  1024   // max row degree ~130 (binomial 8192 @ 1%); big margin

// Scratch (device globals — allocation-free per harness rules)
__device__ __half g_xph[N_NODES * F_OUT];   // 2 MB, x @ W + b in fp16 (gather source)
__device__ float  g_ssrc[N_NODES];
__device__ float  g_sdst[N_NODES];

// ---------------------------------------------------------------------------
// f32x2 packed FMA (Blackwell FFMA2 — 2x fp32 FMA throughput)
// ---------------------------------------------------------------------------
__device__ __forceinline__ unsigned long long fma2(
    unsigned long long a, unsigned long long b, unsigned long long c) {
    unsigned long long d;
    asm("fma.rn.f32x2 %0, %1, %2, %3;" : "=l"(d) : "l"(a), "l"(b), "l"(c));
    return d;
}
__device__ __forceinline__ void unpack2(unsigned long long v, float& a, float& b) {
    asm("mov.b64 {%0, %1}, %2;" : "=f"(a), "=f"(b) : "l"(v));
}

// ---------------------------------------------------------------------------
// Kernel 1: x_prime = x @ W + bias, fused with s_src/s_dst = x_prime . phi.
// 64 rows x 128 cols per CTA, 256 threads, 8x4 outputs/thread as 16 f32x2
// accumulators. W staged DUPLICATED in SMEM so packed operands come straight
// from ulonglong2 LDS (no packing MOVs in the hot loop: 4 LDS + 16 FMA2 / k).
// Register-staged gmem prefetch overlaps loads with compute.
// ---------------------------------------------------------------------------
#define BM 64
#define BK 32
#define XS_LD 68   // padded row (floats); 68*4=272 keeps 16B alignment

__global__ void __launch_bounds__(256) gemm_xp_kernel(
    const float* __restrict__ x, const float* __restrict__ w,
    const float* __restrict__ bias, const float* __restrict__ phi)
{
    __shared__ float xs[BK][XS_LD];   // transposed: xs[k][m]
    __shared__ float wsd[BK][2 * F_OUT];   // duplicated: wsd[k][2n]=wsd[k][2n+1]=w[k][n]

    const int tid  = threadIdx.x;
    const int tx   = tid & 31;   // col group: cols tx*4 .. tx*4+3
    const int ty   = tid >> 5;   // row group: rows ty*8 .. ty*8+7
    const int row0 = blockIdx.x * BM;

    unsigned long long acc[4][4];  // [row-pair p][col j]
    #pragma unroll
    for (int p = 0; p < 4; p++)
        #pragma unroll
        for (int j = 0; j < 4; j++) acc[p][j] = 0ull;

    // prefetch registers
    float4 px[2], pw[4];
    {
        #pragma unroll
        for (int i = 0; i < 2; i++) {
            const int l = tid + i * 256, r = l >> 3, c4 = l & 7;
            px[i] = *(const float4*)(x + (size_t)(row0 + r) * F_IN + c4 * 4);
        }
        #pragma unroll
        for (int i = 0; i < 4; i++)
            pw[i] = ((const float4*)w)[tid + i * 256];
    }

    for (int kt = 0; kt < F_IN / BK; kt++) {
        // stage prefetched chunk into smem
        #pragma unroll
        for (int i = 0; i < 2; i++) {
            const int l = tid + i * 256, r = l >> 3, c4 = l & 7;
            xs[c4 * 4 + 0][r] = px[i].x;
            xs[c4 * 4 + 1][r] = px[i].y;
            xs[c4 * 4 + 2][r] = px[i].z;
            xs[c4 * 4 + 3][r] = px[i].w;
        }
        #pragma unroll
        for (int i = 0; i < 4; i++) {
            const int idx = tid + i * 256;        // float4 index in 32x128 chunk
            const int k = idx >> 5, n0 = (idx & 31) * 4;
            *(float4*)&wsd[k][2 * n0]     = make_float4(pw[i].x, pw[i].x, pw[i].y, pw[i].y);
            *(float4*)&wsd[k][2 * n0 + 4] = make_float4(pw[i].z, pw[i].z, pw[i].w, pw[i].w);
        }
        __syncthreads();

        // prefetch next chunk
        if (kt + 1 < F_IN / BK) {
            const int ko = (kt + 1) * BK;
            #pragma unroll
            for (int i = 0; i < 2; i++) {
                const int l = tid + i * 256, r = l >> 3, c4 = l & 7;
                px[i] = *(const float4*)(x + (size_t)(row0 + r) * F_IN + ko + c4 * 4);
            }
            #pragma unroll
            for (int i = 0; i < 4; i++)
                pw[i] = ((const float4*)(w + (size_t)ko * F_OUT))[tid + i * 256];
        }

        #pragma unroll 8
        for (int k = 0; k < BK; k++) {
            const ulonglong2 xa = *(const ulonglong2*)&xs[k][ty * 8];
            const ulonglong2 xb = *(const ulonglong2*)&xs[k][ty * 8 + 4];
            const ulonglong2 wa = *(const ulonglong2*)&wsd[k][tx * 8];
            const ulonglong2 wb = *(const ulonglong2*)&wsd[k][tx * 8 + 4];
            const unsigned long long xu[4] = {xa.x, xa.y, xb.x, xb.y};
            const unsigned long long w2[4] = {wa.x, wa.y, wb.x, wb.y};
            #pragma unroll
            for (int p = 0; p < 4; p++)
                #pragma unroll
                for (int j = 0; j < 4; j++)
                    acc[p][j] = fma2(xu[p], w2[j], acc[p][j]);
        }
        __syncthreads();
    }

    // ---- epilogue: bias, fp16 store, fused score reductions ----
    float bch[4], phs[4], phd[4];
    #pragma unroll
    for (int j = 0; j < 4; j++) {
        const int c = tx * 4 + j;
        bch[j] = bias[c];
        phs[j] = phi[c];
        phd[j] = phi[F_OUT + c];
    }

    #pragma unroll
    for (int p = 0; p < 4; p++) {
        float v0[4], v1[4];
        #pragma unroll
        for (int j = 0; j < 4; j++) {
            unpack2(acc[p][j], v0[j], v1[j]);
            v0[j] += bch[j];
            v1[j] += bch[j];
        }
        #pragma unroll
        for (int e = 0; e < 2; e++) {
            const float* v = e ? v1 : v0;
            const int row = row0 + ty * 8 + 2 * p + e;
            __half2 h01 = __floats2half2_rn(v[0], v[1]);
            __half2 h23 = __floats2half2_rn(v[2], v[3]);
            uint2 st;
            st.x = reinterpret_cast<unsigned&>(h01);
            st.y = reinterpret_cast<unsigned&>(h23);
            *(uint2*)(g_xph + (size_t)row * F_OUT + tx * 4) = st;

            float ps = v[0] * phs[0] + v[1] * phs[1] + v[2] * phs[2] + v[3] * phs[3];
            float pd = v[0] * phd[0] + v[1] * phd[1] + v[2] * phd[2] + v[3] * phd[3];
            #pragma unroll
            for (int off = 16; off; off >>= 1) {
                ps += __shfl_xor_sync(0xffffffffu, ps, off);
                pd += __shfl_xor_sync(0xffffffffu, pd, off);
            }
            if (tx == 0) { g_ssrc[row] = ps; g_sdst[row] = pd; }
        }
    }
}

// ---------------------------------------------------------------------------
// Kernel 2: per-row attention. One CTA (256 thr) per row.
//  Scan: adj values are exactly 0/1 -> integer nonzero tests (LOP+ISETP).
//        Self-loop pushed unconditionally by thread 0; its adj lane zeroed.
//        Compaction stores (j, w=exp(lrelu(s_src+s_dst))) directly —
//        NO-MAX softmax is exact here (|s| < ~50 << 88, fp32 exp safe;
//        softmax is shift-invariant so result matches reference).
//  Denominator: one warp-shfl sum reduction; 1/sum folded into final write.
//  Gather: interleaved (j,w) pairs (single LDS.64), 8B fp16 loads
//          (32 lanes == full 256B row), 8 neighbor ways, 2-deep ILP.
// ---------------------------------------------------------------------------
__global__ void __launch_bounds__(256) gat_row_kernel(
    const float* __restrict__ adj, float* __restrict__ out)
{
    __shared__ float2 s_pair[MAXNBR];   // {__int_as_float(j), w}
    __shared__ float4 s_acc[256];
    __shared__ float  s_w[12];
    __shared__ int    s_cnt;

    const int row  = blockIdx.x;
    const int tid  = threadIdx.x;
    const int lane = tid & 31;
    const int wid  = tid >> 5;

    const float s_i = g_ssrc[row];
    if (tid == 0) s_cnt = 0;
    __syncthreads();

    // self-loop: always in the mask (adj + eye > 0), pushed exactly once here
    if (tid == 0) {
        float s = s_i + g_sdst[row];
        s = fmaxf(s, 0.2f * s);
        s_pair[atomicAdd(&s_cnt, 1)] = make_float2(__int_as_float(row), __expf(s));
    }

    const uint4* arow = (const uint4*)(adj + (size_t)row * N_NODES);
    const int row_g = row >> 2;

    // ---- scan + compact (2 rounds of 4 front-batched 16B loads) ----
    #pragma unroll
    for (int rnd = 0; rnd < 2; rnd++) {
        uint4 u[4];
        #pragma unroll
        for (int it = 0; it < 4; it++)
            u[it] = __ldcs(&arow[tid + (rnd * 4 + it) * 256]);
        #pragma unroll
        for (int it = 0; it < 4; it++) {
            const int v4 = tid + (rnd * 4 + it) * 256;
            if (v4 == row_g) {      // rare: zero the self lane (already pushed)
                const int r3 = row & 3;
                u[it].x = (r3 == 0) ? 0u : u[it].x;
                u[it].y = (r3 == 1) ? 0u : u[it].y;
                u[it].z = (r3 == 2) ? 0u : u[it].z;
                u[it].w = (r3 == 3) ? 0u : u[it].w;
            }
            if (u[it].x | u[it].y | u[it].z | u[it].w) {
                const int jb = v4 * 4;
                #pragma unroll
                for (int c = 0; c < 4; c++) {
                    const unsigned bits = (c == 0) ? u[it].x : (c == 1) ? u[it].y
                                        : (c == 2) ? u[it].z : u[it].w;
                    if (bits) {
                        const int p = atomicAdd(&s_cnt, 1);
                        if (p < MAXNBR) {
                            const int j = jb + c;
                            float s = s_i + g_sdst[j];
                            s = fmaxf(s, 0.2f * s);
                            s_pair[p] = make_float2(__int_as_float(j), __expf(s));
                        }
                    }
                }
            }
        }
    }
    __syncthreads();
    const int cnt = min(s_cnt, MAXNBR);

    // ---- denominator: sum of weights ----
    float sm = 0.0f;
    for (int k = tid; k < cnt; k += 256) sm += s_pair[k].y;
    #pragma unroll
    for (int off = 16; off; off >>= 1)
        sm += __shfl_xor_sync(0xffffffffu, sm, off);
    if (lane == 0) s_w[wid] = sm;
    __syncthreads();
    if (tid == 0) {
        float s = 0.0f;
        #pragma unroll
        for (int i = 0; i < 8; i++) s += s_w[i];
        s_w[8] = 1.0f / s;    // >= 1 term always (self-loop)
    }
    __syncthreads();
    const float inv = s_w[8];

    // ---- fp16 weighted gather: 8 ways x 32 lanes (4 halves each) ----
    const int way = tid >> 5;                    // neighbor way 0..7
    const uint2* xp2 = (const uint2*)g_xph;      // 32 uint2 per row
    float4 acc = make_float4(0.f, 0.f, 0.f, 0.f);

    int k = way;
    for (; k + 8 < cnt; k += 16) {
        const float2 p0 = s_pair[k];
        const float2 p1 = s_pair[k + 8];
        const uint2 v0 = xp2[(size_t)__float_as_int(p0.x) * 32 + lane];
        const uint2 v1 = xp2[(size_t)__float_as_int(p1.x) * 32 + lane];
        const float2 a0 = __half22float2(*(const __half2*)&v0.x);
        const float2 b0 = __half22float2(*(const __half2*)&v0.y);
        const float2 a1 = __half22float2(*(const __half2*)&v1.x);
        const float2 b1 = __half22float2(*(const __half2*)&v1.y);
        acc.x = fmaf(p0.y, a0.x, acc.x); acc.y = fmaf(p0.y, a0.y, acc.y);
        acc.z = fmaf(p0.y, b0.x, acc.z); acc.w = fmaf(p0.y, b0.y, acc.w);
        acc.x = fmaf(p1.y, a1.x, acc.x); acc.y = fmaf(p1.y, a1.y, acc.y);
        acc.z = fmaf(p1.y, b1.x, acc.z); acc.w = fmaf(p1.y, b1.y, acc.w);
    }
    for (; k < cnt; k += 8) {
        const float2 p0 = s_pair[k];
        const uint2 v0 = xp2[(size_t)__float_as_int(p0.x) * 32 + lane];
        const float2 a0 = __half22float2(*(const __half2*)&v0.x);
        const float2 b0 = __half22float2(*(const __half2*)&v0.y);
        acc.x = fmaf(p0.y, a0.x, acc.x); acc.y = fmaf(p0.y, a0.y, acc.y);
        acc.z = fmaf(p0.y, b0.x, acc.z); acc.w = fmaf(p0.y, b0.y, acc.w);
    }
    s_acc[tid] = acc;
    __syncthreads();

    // cross-way reduction tree
    if (tid < 128) {
        const float4 o = s_acc[tid + 128];
        acc = s_acc[tid];
        acc.x += o.x; acc.y += o.y; acc.z += o.z; acc.w += o.w;
        s_acc[tid] = acc;
    }
    __syncthreads();
    if (tid < 64) {
        const float4 o = s_acc[tid + 64];
        acc = s_acc[tid];
        acc.x += o.x; acc.y += o.y; acc.z += o.z; acc.w += o.w;
        s_acc[tid] = acc;
    }
    __syncthreads();
    if (tid < 32) {
        const float4 a = s_acc[tid];
        const float4 b = s_acc[tid + 32];
        float4 r;
        r.x = (a.x + b.x) * inv;
        r.y = (a.y + b.y) * inv;
        r.z = (a.z + b.z) * inv;
        r.w = (a.w + b.w) * inv;
        *(float4*)(out + (size_t)row * F_OUT + tid * 4) = r;
    }
}

// ---------------------------------------------------------------------------
extern "C" void kernel_launch(void* const* d_in, const int* in_sizes, int n_in,
                              void* d_out, int out_size)
{
    const float* adj  = (const float*)d_in[0];   // [8192, 8192]
    const float* x    = (const float*)d_in[1];   // [8192, 256]
    const float* w    = (const float*)d_in[2];   // [256, 128]
    const float* bias = (const float*)d_in[3];   // [128]
    const float* phi  = (const float*)d_in[4];   // [256, 1]
    float* out = (float*)d_out;                  // [8192, 128]

    gemm_xp_kernel<<<N_NODES / BM, 256>>>(x, w, bias, phi);
    gat_row_kernel<<<N_NODES, 256>>>(adj, out);
}